// round 15
// baseline (speedup 1.0000x reference)
#include <cuda_runtime.h>
#include <cuda_fp16.h>
#include <math.h>
#include <stdint.h>

#define TSEQ 1536
#define HID  2880
#define NHEAD 64
#define NKVH  8
#define DH    64
#define QC   (NHEAD*DH)        /* 4096 */
#define KVC  (NKVH*DH)         /* 512  */
#define NTOT (QC + 2*KVC)      /* 5120 */
#define NOUT 2880
#define NOUT_PAD 2944          /* 23*128 */

#define L2THETA_OVER_32 0.53733134f

// ---------------- device-global scratch (zero-initialized) -------------------
__device__ __half g_Xh[(size_t)TSEQ*HID];
__device__ __half g_WTh[(size_t)NTOT*HID];     // qkv weights [n][k]
__device__ __half g_WoTh[(size_t)NOUT_PAD*QC]; // out weights [n][k], pad rows stay 0
__device__ __half g_Qh[(size_t)TSEQ*QC];
__device__ __half g_Kh[(size_t)TSEQ*KVC];
__device__ __half g_Vh[(size_t)TSEQ*KVC];
__device__ __half g_Yh[(size_t)TSEQ*QC];

// ---------------- helpers ----------------------------------------------------
__device__ __forceinline__ void mma_f16(float c[4], const uint32_t a[4], const uint32_t b[2]) {
    asm volatile(
        "mma.sync.aligned.m16n8k16.row.col.f32.f16.f16.f32 "
        "{%0,%1,%2,%3}, {%4,%5,%6,%7}, {%8,%9}, {%0,%1,%2,%3};"
        : "+f"(c[0]), "+f"(c[1]), "+f"(c[2]), "+f"(c[3])
        : "r"(a[0]), "r"(a[1]), "r"(a[2]), "r"(a[3]), "r"(b[0]), "r"(b[1]));
}
__device__ __forceinline__ void ldsm_x4(uint32_t r[4], uint32_t addr) {
    asm volatile("ldmatrix.sync.aligned.m8n8.x4.shared.b16 {%0,%1,%2,%3}, [%4];"
        : "=r"(r[0]), "=r"(r[1]), "=r"(r[2]), "=r"(r[3]) : "r"(addr));
}
__device__ __forceinline__ uint32_t smem_u32(const void* p) {
    uint32_t a;
    asm("{ .reg .u64 t; cvta.to.shared.u64 t, %1; cvt.u32.u64 %0, t; }" : "=r"(a) : "l"(p));
    return a;
}
__device__ __forceinline__ void cp16(uint32_t s, const void* g) {
    asm volatile("cp.async.cg.shared.global [%0], [%1], 16;" :: "r"(s), "l"(g));
}
#define CP_COMMIT() asm volatile("cp.async.commit_group;" ::: "memory")
#define CP_WAIT1()  asm volatile("cp.async.wait_group 1;" ::: "memory")

__device__ __forceinline__ uint32_t h2u(__half2 h) { return *(uint32_t*)&h; }

#define BK     64                      /* halves per k-chunk */
#define PAD_H  72                      /* 144B = 9x16B rows -> LDSM conflict-free */
#define A_BYTES (128*PAD_H*2)          /* 18432 */
#define STAGE_BYTES (2*A_BYTES)        /* 36864 */
#define GEMM_SMEM   (3*STAGE_BYTES)    /* 110592 */
#define GEMM_THREADS 256               /* 8 warps of 32x64 */

// ---------------- prep: conv_x (uint4 stores) + 64x64 transpose_qkv ----------
#define CONV_B (TSEQ*HID/2048)         /* 2160: 8 floats per thread */
#define TQ_BX  (NTOT/64)               /* 80 */
#define TQ_B   (TQ_BX*(HID/64))        /* 3600 */
#define PREP_B (CONV_B + TQ_B)

__global__ __launch_bounds__(256) void prep_qkv(
    const float* __restrict__ x,
    const float* __restrict__ Wq, const float* __restrict__ Wk,
    const float* __restrict__ Wv)
{
    __shared__ float tile[64][65];
    const int b = blockIdx.x, tid = threadIdx.x;

    if (b < CONV_B) {
        const size_t i = ((size_t)b * 256 + tid) * 8;
        float4 v0 = *(const float4*)(x + i);
        float4 v1 = *(const float4*)(x + i + 4);
        uint4 o;
        o.x = h2u(__floats2half2_rn(v0.x, v0.y));
        o.y = h2u(__floats2half2_rn(v0.z, v0.w));
        o.z = h2u(__floats2half2_rn(v1.x, v1.y));
        o.w = h2u(__floats2half2_rn(v1.z, v1.w));
        *(uint4*)(g_Xh + i) = o;
        return;
    }

    const int bb = b - CONV_B;
    const int n0 = (bb % TQ_BX) * 64, k0 = (bb / TQ_BX) * 64;
    const float* src; int ld, nb;
    if (n0 < QC)            { src = Wq; ld = QC;  nb = n0; }
    else if (n0 < QC + KVC) { src = Wk; ld = KVC; nb = n0 - QC; }
    else                    { src = Wv; ld = KVC; nb = n0 - QC - KVC; }

    // load 64x64 fp32 tile (coalesced rows)
    {
        const int tx = tid & 63, ty = tid >> 6;
        #pragma unroll
        for (int i = 0; i < 64; i += 4)
            tile[ty + i][tx] = src[(size_t)(k0 + ty + i) * ld + nb + tx];
    }
    __syncthreads();
    // store transposed: 4 halves (uint2) per thread per pass -> 8B stores
    {
        const int c4 = tid & 15, rb = tid >> 4;   // quad-col, row-base
        #pragma unroll
        for (int i = 0; i < 4; i++) {
            const int r = rb + 16 * i;
            uint2 o;
            o.x = h2u(__floats2half2_rn(tile[4*c4    ][r], tile[4*c4 + 1][r]));
            o.y = h2u(__floats2half2_rn(tile[4*c4 + 2][r], tile[4*c4 + 3][r]));
            *(uint2*)(g_WTh + (size_t)(n0 + r) * HID + k0 + 4*c4) = o;
        }
    }
}

// ---------------- GEMM mainloop (R12 config, unchanged) ----------------------
__device__ __forceinline__ void gemm_mainloop_f16(
    const __half* __restrict__ Ag, const __half* __restrict__ Bg,
    int m0, int n0, int K,
    float (&acc)[2][8][4], char* sm)
{
    const int tid  = threadIdx.x;
    const int lane = tid & 31;
    const int wid  = tid >> 5;              // 0..7
    const int warp_m = wid & 3, warp_n = wid >> 2;   // 4m x 2n
    const uint32_t sbase = smem_u32(sm);

    const int a_row = warp_m * 32 + (lane & 15);
    const int a_col = (lane >> 4) << 3;
    const int b_row = warp_n * 64 + ((lane >> 4) << 3) + (lane & 7);
    const int b_col = ((lane >> 3) & 1) << 3;

    int rr_[4], ff_[4];
    #pragma unroll
    for (int i = 0; i < 4; i++) {
        int idx = i * 256 + tid;
        rr_[i] = idx >> 3;
        ff_[i] = (idx & 7) * 8;
    }

    const int NK = K / BK;

    #define ISSUE_FULL(s, kc) do { \
        const uint32_t a_s = sbase + (s) * STAGE_BYTES; \
        const int kof = (kc) * BK; \
        _Pragma("unroll") \
        for (int i = 0; i < 4; i++) { \
            cp16(a_s + (rr_[i] * PAD_H + ff_[i]) * 2,           Ag + (size_t)(m0 + rr_[i]) * K + kof + ff_[i]); \
            cp16(a_s + A_BYTES + (rr_[i] * PAD_H + ff_[i]) * 2, Bg + (size_t)(n0 + rr_[i]) * K + kof + ff_[i]); \
        } \
        CP_COMMIT(); \
    } while (0)

    ISSUE_FULL(0, 0);
    ISSUE_FULL(1, 1);

    uint32_t afb[2][2][4];
    uint32_t bfb[2][4];

    for (int kc = 0; kc < NK; kc++) {
        CP_WAIT1();
        __syncthreads();

        const uint32_t as_b = sbase + (kc % 3) * STAGE_BYTES;
        const uint32_t bs_b = as_b + A_BYTES;
        const uint32_t wr_s = sbase + ((kc + 2) % 3) * STAGE_BYTES;
        const bool do_issue = (kc + 2 < NK);
        const int kof = (kc + 2) * BK;

        ldsm_x4(afb[0][0], as_b + ((a_row       * PAD_H) + a_col) * 2);
        ldsm_x4(afb[0][1], as_b + (((a_row + 16) * PAD_H) + a_col) * 2);
        ldsm_x4(bfb[0],    bs_b + ((b_row       * PAD_H) + b_col) * 2);

        #pragma unroll
        for (int ks16 = 0; ks16 < 4; ks16++) {
            const int ks = ks16 * 16;
            if (do_issue) {
                cp16(wr_s + (rr_[ks16] * PAD_H + ff_[ks16]) * 2,
                     Ag + (size_t)(m0 + rr_[ks16]) * K + kof + ff_[ks16]);
                cp16(wr_s + A_BYTES + (rr_[ks16] * PAD_H + ff_[ks16]) * 2,
                     Bg + (size_t)(n0 + rr_[ks16]) * K + kof + ff_[ks16]);
            }
            #pragma unroll
            for (int p = 0; p < 4; p++) {
                if (p < 3)
                    ldsm_x4(bfb[(p + 1) & 1],
                            bs_b + (((b_row + (p + 1) * 16) * PAD_H) + ks + b_col) * 2);
                else if (ks16 < 3)
                    ldsm_x4(bfb[0],
                            bs_b + ((b_row * PAD_H) + ks + 16 + b_col) * 2);
                if (p == 0 && ks16 < 3) {
                    ldsm_x4(afb[(ks16 + 1) & 1][0],
                            as_b + ((a_row * PAD_H) + ks + 16 + a_col) * 2);
                    ldsm_x4(afb[(ks16 + 1) & 1][1],
                            as_b + (((a_row + 16) * PAD_H) + ks + 16 + a_col) * 2);
                }
                const uint32_t* bfc = bfb[p & 1];
                mma_f16(acc[0][2*p],     afb[ks16 & 1][0], &bfc[0]);
                mma_f16(acc[0][2*p + 1], afb[ks16 & 1][0], &bfc[2]);
                mma_f16(acc[1][2*p],     afb[ks16 & 1][1], &bfc[0]);
                mma_f16(acc[1][2*p + 1], afb[ks16 & 1][1], &bfc[2]);
            }
        }
        CP_COMMIT();
    }
    #undef ISSUE_FULL
}

// ---------------- QKV projection (+bias, +RoPE) + Wo transpose tail ----------
#define QKV_BX (NTOT/128)              /* 40 */
#define QKV_B  (QKV_BX*(TSEQ/128))     /* 480 */
#define WO_BX  (NOUT/64)               /* 45 */
#define WO_B   (WO_BX*(QC/64))         /* 2880 */

__global__ __launch_bounds__(GEMM_THREADS) void qkv_mma(
    const int* __restrict__ positions,
    const float* __restrict__ bq, const float* __restrict__ bk,
    const float* __restrict__ bv, const float* __restrict__ Wo)
{
    extern __shared__ char sm[];
    const int tid  = threadIdx.x;

    if (blockIdx.x >= QKV_B) {
        // ---- Wo 64x64 transpose tile (backfills qkv's idle wave-2 slots) ----
        float (*tile)[65] = (float(*)[65])sm;
        const int bb = blockIdx.x - QKV_B;
        const int n0 = (bb % WO_BX) * 64, k0 = (bb / WO_BX) * 64;
        {
            const int tx = tid & 63, ty = tid >> 6;
            #pragma unroll
            for (int i = 0; i < 64; i += 4)
                tile[ty + i][tx] = Wo[(size_t)(k0 + ty + i) * NOUT + n0 + tx];
        }
        __syncthreads();
        {
            const int c4 = tid & 15, rb = tid >> 4;
            #pragma unroll
            for (int i = 0; i < 4; i++) {
                const int r = rb + 16 * i;
                uint2 o;
                o.x = h2u(__floats2half2_rn(tile[4*c4    ][r], tile[4*c4 + 1][r]));
                o.y = h2u(__floats2half2_rn(tile[4*c4 + 2][r], tile[4*c4 + 3][r]));
                *(uint2*)(g_WoTh + (size_t)(n0 + r) * QC + k0 + 4*c4) = o;
            }
        }
        return;
    }

    const int lane = tid & 31;
    const int wid  = tid >> 5;
    const int warp_m = wid & 3, warp_n = wid >> 2;
    const int gid = lane >> 2, tig = lane & 3;
    const int m0 = (blockIdx.x / QKV_BX) * 128, n0 = (blockIdx.x % QKV_BX) * 128;

    const float* bias; __half* outp; int ldout, nloc0, do_rope;
    if (n0 < QC)            { bias = bq; outp = g_Qh; ldout = QC;  nloc0 = n0;            do_rope = 1; }
    else if (n0 < QC + KVC) { bias = bk; outp = g_Kh; ldout = KVC; nloc0 = n0 - QC;       do_rope = 1; }
    else                    { bias = bv; outp = g_Vh; ldout = KVC; nloc0 = n0 - QC - KVC; do_rope = 0; }

    float acc[2][8][4];
    #pragma unroll
    for (int a = 0; a < 2; a++)
        #pragma unroll
        for (int b = 0; b < 8; b++)
            #pragma unroll
            for (int d = 0; d < 4; d++) acc[a][b][d] = 0.f;

    gemm_mainloop_f16(g_Xh, g_WTh, m0, n0, HID, acc, sm);

    #pragma unroll
    for (int mt = 0; mt < 2; mt++) {
        const int t_lo = m0 + warp_m * 32 + mt * 16 + gid;
        const int t_hi = t_lo + 8;
        float pos_lo = 0.f, pos_hi = 0.f;
        if (do_rope) { pos_lo = (float)positions[t_lo]; pos_hi = (float)positions[t_hi]; }
        #pragma unroll
        for (int nt = 0; nt < 8; nt++) {
            const int c = nloc0 + warp_n * 64 + nt * 8 + 2 * tig;
            const float b0 = bias[c], b1 = bias[c + 1];
            float v0 = acc[mt][nt][0] + b0, v1 = acc[mt][nt][1] + b1;
            float v2 = acc[mt][nt][2] + b0, v3 = acc[mt][nt][3] + b1;
            if (do_rope) {
                const int ip = (c & (DH - 1)) >> 1;
                const float inv_eff = 0.515625f * exp2f(-(float)ip * L2THETA_OVER_32);
                float s, co;
                __sincosf(pos_lo * (1.0f / 32.0f) * inv_eff, &s, &co);
                float e = v0 * co - v1 * s; v1 = v0 * s + v1 * co; v0 = e;
                __sincosf(pos_hi * (1.0f / 32.0f) * inv_eff, &s, &co);
                e = v2 * co - v3 * s; v3 = v2 * s + v3 * co; v2 = e;
            }
            *(__half2*)(outp + (size_t)t_lo * ldout + c) = __floats2half2_rn(v0, v1);
            *(__half2*)(outp + (size_t)t_hi * ldout + c) = __floats2half2_rn(v2, v3);
        }
    }
}

// ---------------- output projection (+bias) ----------------------------------
__global__ __launch_bounds__(GEMM_THREADS) void out_mma(
    const float* __restrict__ bo, float* __restrict__ out)
{
    extern __shared__ char sm[];
    const int tid  = threadIdx.x;
    const int lane = tid & 31;
    const int wid  = tid >> 5;
    const int warp_m = wid & 3, warp_n = wid >> 2;
    const int gid = lane >> 2, tig = lane & 3;
    const int m0 = blockIdx.y * 128, n0 = blockIdx.x * 128;

    float acc[2][8][4];
    #pragma unroll
    for (int a = 0; a < 2; a++)
        #pragma unroll
        for (int b = 0; b < 8; b++)
            #pragma unroll
            for (int d = 0; d < 4; d++) acc[a][b][d] = 0.f;

    gemm_mainloop_f16(g_Yh, g_WoTh, m0, n0, QC, acc, sm);

    #pragma unroll
    for (int mt = 0; mt < 2; mt++) {
        const int t_lo = m0 + warp_m * 32 + mt * 16 + gid;
        const int t_hi = t_lo + 8;
        #pragma unroll
        for (int nt = 0; nt < 8; nt++) {
            const int c = n0 + warp_n * 64 + nt * 8 + 2 * tig;
            if (c < NOUT) {
                const float b0 = bo[c], b1 = bo[c + 1];
                *(float2*)(out + (size_t)t_lo * NOUT + c) =
                    make_float2(acc[mt][nt][0] + b0, acc[mt][nt][1] + b1);
                *(float2*)(out + (size_t)t_hi * NOUT + c) =
                    make_float2(acc[mt][nt][2] + b0, acc[mt][nt][3] + b1);
            }
        }
    }
}

// ---------------- flash attention: 2 heads/block (shared KV) -----------------
#define KS_H2 72
#define VT_H2 72
#define PS_H2 72
#define AOFF_VT (64*KS_H2*2)
#define AOFF_PS (AOFF_VT + 64*VT_H2*2)
#define PS_HEAD_BYTES (64*PS_H2*2)
#define ATT_SMEM (AOFF_PS + 2*PS_HEAD_BYTES)   /* 36864 */
#define NQB    (TSEQ/64)                        /* 24 */
#define ATT_B  (NQB*(NHEAD/2))                  /* 768 */

__global__ __launch_bounds__(256) void attn_mma(
    const int* __restrict__ is_slide_p, const int* __restrict__ win_p)
{
    extern __shared__ char sm[];
    const int tid = threadIdx.x;

    __half (*Ks)[KS_H2] = (__half(*)[KS_H2])(sm);
    __half (*Vt)[VT_H2] = (__half(*)[VT_H2])(sm + AOFF_VT);
    const uint32_t ks_b = smem_u32(sm);
    const uint32_t vt_b = ks_b + AOFF_VT;

    const int lane = tid & 31, wid = tid >> 5;   // 8 warps
    const int wid4 = wid & 3, hsel = wid >> 2;   // 4 warps per head
    const int gid = lane >> 2, tig = lane & 3;
    const int t0   = (blockIdx.x % NQB) * 64;
    const int pair = blockIdx.x / NQB;           // 0..31
    const int h    = 2 * pair + hsel;
    const int kvh  = pair >> 2;
    const int is_slide = is_slide_p[0], W = win_p[0];

    __half (*Ps)[PS_H2] = (__half(*)[PS_H2])(sm + AOFF_PS + hsel * PS_HEAD_BYTES);
    const uint32_t ps_b = ks_b + AOFF_PS + hsel * PS_HEAD_BYTES;

    const int r0 = t0 + wid4 * 16 + gid, r1 = r0 + 8;
    const int rlo0 = is_slide ? r0 - W : 0;
    const int rlo1 = is_slide ? r1 - W : 0;
    const int lrow = wid4 * 16 + gid;

    const int ld_row16 = lane & 15;
    const int ld_koff  = (lane >> 4) << 3;
    const int ld_nrow  = ((lane >> 4) << 3) + (lane & 7);
    const int ld_bkoff = ((lane >> 3) & 1) << 3;

    uint32_t qf[4][4];
    {
        const __half* q0 = g_Qh + (size_t)r0 * QC + h * DH;
        const __half* q1 = g_Qh + (size_t)r1 * QC + h * DH;
        #pragma unroll
        for (int kk = 0; kk < 4; kk++) {
            qf[kk][0] = *(const uint32_t*)(q0 + kk * 16 + 2 * tig);
            qf[kk][1] = *(const uint32_t*)(q1 + kk * 16 + 2 * tig);
            qf[kk][2] = *(const uint32_t*)(q0 + kk * 16 + 2 * tig + 8);
            qf[kk][3] = *(const uint32_t*)(q1 + kk * 16 + 2 * tig + 8);
        }
    }

    float oc[8][4];
    #pragma unroll
    for (int nt = 0; nt < 8; nt++)
        #pragma unroll
        for (int d = 0; d < 4; d++) oc[nt][d] = 0.f;
    float m0v = -1e30f, m1v = -1e30f, l0 = 0.f, l1 = 0.f;

    const int cs0 = is_slide ? (max(0, t0 - W) & ~63) : 0;

    for (int cs = cs0; cs <= t0; cs += 64) {
        __syncthreads();
        #pragma unroll
        for (int i = 0; i < 2; i++) {
            int idx = i * 256 + tid, rr = idx >> 3, c8 = (idx & 7) * 8;
            *(uint4*)&Ks[rr][c8] =
                *(const uint4*)(g_Kh + (size_t)(cs + rr) * KVC + kvh * DH + c8);
            union { uint4 u; __half hv[8]; } v;
            v.u = *(const uint4*)(g_Vh + (size_t)(cs + rr) * KVC + kvh * DH + c8);
            #pragma unroll
            for (int j = 0; j < 8; j++) Vt[c8 + j][rr] = v.hv[j];
        }
        __syncthreads();

        float sc[8][4];
        #pragma unroll
        for (int p = 0; p < 4; p++) {
            sc[2*p][0] = sc[2*p][1] = sc[2*p][2] = sc[2*p][3] = 0.f;
            sc[2*p+1][0] = sc[2*p+1][1] = sc[2*p+1][2] = sc[2*p+1][3] = 0.f;
            #pragma unroll
            for (int kk = 0; kk < 4; kk++) {
                uint32_t bf[4];
                ldsm_x4(bf, ks_b + (((p * 16 + ld_nrow) * KS_H2) + kk * 16 + ld_bkoff) * 2);
                mma_f16(sc[2*p],     qf[kk], &bf[0]);
                mma_f16(sc[2*p + 1], qf[kk], &bf[2]);
            }
        }

        float vmax0 = -1e30f, vmax1 = -1e30f;
        #pragma unroll
        for (int nt = 0; nt < 8; nt++) {
            const int s0 = cs + nt * 8 + 2 * tig, s1 = s0 + 1;
            float v0 = (s0 <= r0 && s0 >= rlo0) ? sc[nt][0] * 0.125f : -1e30f;
            float v1 = (s1 <= r0 && s1 >= rlo0) ? sc[nt][1] * 0.125f : -1e30f;
            float v2 = (s0 <= r1 && s0 >= rlo1) ? sc[nt][2] * 0.125f : -1e30f;
            float v3 = (s1 <= r1 && s1 >= rlo1) ? sc[nt][3] * 0.125f : -1e30f;
            sc[nt][0] = v0; sc[nt][1] = v1; sc[nt][2] = v2; sc[nt][3] = v3;
            vmax0 = fmaxf(vmax0, fmaxf(v0, v1));
            vmax1 = fmaxf(vmax1, fmaxf(v2, v3));
        }
        vmax0 = fmaxf(vmax0, __shfl_xor_sync(0xffffffffu, vmax0, 1));
        vmax0 = fmaxf(vmax0, __shfl_xor_sync(0xffffffffu, vmax0, 2));
        vmax1 = fmaxf(vmax1, __shfl_xor_sync(0xffffffffu, vmax1, 1));
        vmax1 = fmaxf(vmax1, __shfl_xor_sync(0xffffffffu, vmax1, 2));

        const float mn0 = fmaxf(m0v, vmax0), mn1 = fmaxf(m1v, vmax1);
        const float a0 = __expf(m0v - mn0), a1 = __expf(m1v - mn1);
        m0v = mn0; m1v = mn1;

        float ps0 = 0.f, ps1 = 0.f;
        #pragma unroll
        for (int nt = 0; nt < 8; nt++) {
            float p0 = __expf(sc[nt][0] - mn0), p1 = __expf(sc[nt][1] - mn0);
            float p2 = __expf(sc[nt][2] - mn1), p3 = __expf(sc[nt][3] - mn1);
            ps0 += p0 + p1; ps1 += p2 + p3;
            *(__half2*)&Ps[lrow][nt * 8 + 2 * tig] = __floats2half2_rn(p0, p1);
            *(__half2*)&Ps[lrow + 8][nt * 8 + 2 * tig] = __floats2half2_rn(p2, p3);
        }
        ps0 += __shfl_xor_sync(0xffffffffu, ps0, 1);
        ps0 += __shfl_xor_sync(0xffffffffu, ps0, 2);
        ps1 += __shfl_xor_sync(0xffffffffu, ps1, 1);
        ps1 += __shfl_xor_sync(0xffffffffu, ps1, 2);
        l0 = l0 * a0 + ps0;
        l1 = l1 * a1 + ps1;

        #pragma unroll
        for (int nt = 0; nt < 8; nt++) {
            oc[nt][0] *= a0; oc[nt][1] *= a0;
            oc[nt][2] *= a1; oc[nt][3] *= a1;
        }
        __syncwarp();

        #pragma unroll
        for (int kk = 0; kk < 4; kk++) {
            uint32_t af[4];
            ldsm_x4(af, ps_b + (((wid4 * 16 + ld_row16) * PS_H2) + kk * 16 + ld_koff) * 2);
            #pragma unroll
            for (int p = 0; p < 4; p++) {
                uint32_t bf[4];
                ldsm_x4(bf, vt_b + (((p * 16 + ld_nrow) * VT_H2) + kk * 16 + ld_bkoff) * 2);
                mma_f16(oc[2*p],     af, &bf[0]);
                mma_f16(oc[2*p + 1], af, &bf[2]);
            }
        }
    }

    const float i0 = 1.f / l0, i1 = 1.f / l1;
    #pragma unroll
    for (int nt = 0; nt < 8; nt++) {
        const int c = h * DH + nt * 8 + 2 * tig;
        *(__half2*)(g_Yh + (size_t)r0 * QC + c) =
            __floats2half2_rn(oc[nt][0] * i0, oc[nt][1] * i0);
        *(__half2*)(g_Yh + (size_t)r1 * QC + c) =
            __floats2half2_rn(oc[nt][2] * i1, oc[nt][3] * i1);
    }
}

// ---------------------------------------------------------------------------
extern "C" void kernel_launch(void* const* d_in, const int* in_sizes, int n_in,
                              void* d_out, int out_size)
{
    const float* x         = (const float*)d_in[0];
    const int*   positions = (const int*)  d_in[1];
    const float* Wq        = (const float*)d_in[2];
    const float* bq        = (const float*)d_in[3];
    const float* Wk        = (const float*)d_in[4];
    const float* bk        = (const float*)d_in[5];
    const float* Wv        = (const float*)d_in[6];
    const float* bv        = (const float*)d_in[7];
    const float* Wo        = (const float*)d_in[8];
    const float* bo        = (const float*)d_in[9];
    const int*   is_slide  = (const int*)  d_in[10];
    const int*   win       = (const int*)  d_in[11];

    cudaFuncSetAttribute(attn_mma, cudaFuncAttributeMaxDynamicSharedMemorySize, ATT_SMEM);
    cudaFuncSetAttribute(qkv_mma,  cudaFuncAttributeMaxDynamicSharedMemorySize, GEMM_SMEM);
    cudaFuncSetAttribute(out_mma,  cudaFuncAttributeMaxDynamicSharedMemorySize, GEMM_SMEM);

    prep_qkv<<<PREP_B, 256>>>(x, Wq, Wk, Wv);

    qkv_mma<<<QKV_B + WO_B, GEMM_THREADS, GEMM_SMEM>>>(positions, bq, bk, bv, Wo);

    attn_mma<<<ATT_B, 256, ATT_SMEM>>>(is_slide, win);

    out_mma<<<dim3(NOUT_PAD / 128, TSEQ / 128), GEMM_THREADS, GEMM_SMEM>>>(bo, (float*)d_out);
}

// round 16
// speedup vs baseline: 1.0432x; 1.0432x over previous
#include <cuda_runtime.h>
#include <cuda_fp16.h>
#include <math.h>
#include <stdint.h>

#define TSEQ 1536
#define HID  2880
#define NHEAD 64
#define NKVH  8
#define DH    64
#define QC   (NHEAD*DH)        /* 4096 */
#define KVC  (NKVH*DH)         /* 512  */
#define NTOT (QC + 2*KVC)      /* 5120 */
#define NOUT 2880
#define NOUT_PAD 2944          /* 23*128 */

#define L2THETA_OVER_32 0.53733134f

// ---------------- device-global scratch (zero-initialized) -------------------
__device__ __half g_Xh[(size_t)TSEQ*HID];
__device__ __half g_WTh[(size_t)NTOT*HID];     // qkv weights [n][k]
__device__ __half g_WoTh[(size_t)NOUT_PAD*QC]; // out weights [n][k], pad rows stay 0
__device__ __half g_Qh[(size_t)TSEQ*QC];
__device__ __half g_Kh[(size_t)TSEQ*KVC];
__device__ __half g_Vh[(size_t)TSEQ*KVC];
__device__ __half g_Yh[(size_t)TSEQ*QC];

// ---------------- helpers ----------------------------------------------------
__device__ __forceinline__ void mma_f16(float c[4], const uint32_t a[4], const uint32_t b[2]) {
    asm volatile(
        "mma.sync.aligned.m16n8k16.row.col.f32.f16.f16.f32 "
        "{%0,%1,%2,%3}, {%4,%5,%6,%7}, {%8,%9}, {%0,%1,%2,%3};"
        : "+f"(c[0]), "+f"(c[1]), "+f"(c[2]), "+f"(c[3])
        : "r"(a[0]), "r"(a[1]), "r"(a[2]), "r"(a[3]), "r"(b[0]), "r"(b[1]));
}
__device__ __forceinline__ void ldsm_x4(uint32_t r[4], uint32_t addr) {
    asm volatile("ldmatrix.sync.aligned.m8n8.x4.shared.b16 {%0,%1,%2,%3}, [%4];"
        : "=r"(r[0]), "=r"(r[1]), "=r"(r[2]), "=r"(r[3]) : "r"(addr));
}
__device__ __forceinline__ void ldsm_x4_trans(uint32_t r[4], uint32_t addr) {
    asm volatile("ldmatrix.sync.aligned.m8n8.x4.trans.shared.b16 {%0,%1,%2,%3}, [%4];"
        : "=r"(r[0]), "=r"(r[1]), "=r"(r[2]), "=r"(r[3]) : "r"(addr));
}
__device__ __forceinline__ uint32_t smem_u32(const void* p) {
    uint32_t a;
    asm("{ .reg .u64 t; cvta.to.shared.u64 t, %1; cvt.u32.u64 %0, t; }" : "=r"(a) : "l"(p));
    return a;
}
__device__ __forceinline__ void cp16(uint32_t s, const void* g) {
    asm volatile("cp.async.cg.shared.global [%0], [%1], 16;" :: "r"(s), "l"(g));
}
#define CP_COMMIT() asm volatile("cp.async.commit_group;" ::: "memory")
#define CP_WAIT1()  asm volatile("cp.async.wait_group 1;" ::: "memory")

__device__ __forceinline__ uint32_t h2u(__half2 h) { return *(uint32_t*)&h; }

#define BK     64                      /* halves per k-chunk */
#define PAD_H  72                      /* 144B = 9x16B rows -> LDSM conflict-free */
#define A_BYTES (128*PAD_H*2)          /* 18432 */
#define STAGE_BYTES (2*A_BYTES)        /* 36864 */
#define GEMM_SMEM   (3*STAGE_BYTES)    /* 110592 */
#define GEMM_THREADS 256               /* 8 warps of 32x64 */

// ---------------- prep: conv_x (uint4 stores) + 64x64 transpose_qkv ----------
#define CONV_B (TSEQ*HID/2048)         /* 2160: 8 floats per thread */
#define TQ_BX  (NTOT/64)               /* 80 */
#define TQ_B   (TQ_BX*(HID/64))        /* 3600 */
#define PREP_B (CONV_B + TQ_B)

__global__ __launch_bounds__(256) void prep_qkv(
    const float* __restrict__ x,
    const float* __restrict__ Wq, const float* __restrict__ Wk,
    const float* __restrict__ Wv)
{
    __shared__ float tile[64][65];
    const int b = blockIdx.x, tid = threadIdx.x;

    if (b < CONV_B) {
        const size_t i = ((size_t)b * 256 + tid) * 8;
        float4 v0 = *(const float4*)(x + i);
        float4 v1 = *(const float4*)(x + i + 4);
        uint4 o;
        o.x = h2u(__floats2half2_rn(v0.x, v0.y));
        o.y = h2u(__floats2half2_rn(v0.z, v0.w));
        o.z = h2u(__floats2half2_rn(v1.x, v1.y));
        o.w = h2u(__floats2half2_rn(v1.z, v1.w));
        *(uint4*)(g_Xh + i) = o;
        return;
    }

    const int bb = b - CONV_B;
    const int n0 = (bb % TQ_BX) * 64, k0 = (bb / TQ_BX) * 64;
    const float* src; int ld, nb;
    if (n0 < QC)            { src = Wq; ld = QC;  nb = n0; }
    else if (n0 < QC + KVC) { src = Wk; ld = KVC; nb = n0 - QC; }
    else                    { src = Wv; ld = KVC; nb = n0 - QC - KVC; }

    {
        const int tx = tid & 63, ty = tid >> 6;
        #pragma unroll
        for (int i = 0; i < 64; i += 4)
            tile[ty + i][tx] = src[(size_t)(k0 + ty + i) * ld + nb + tx];
    }
    __syncthreads();
    {
        const int c4 = tid & 15, rb = tid >> 4;
        #pragma unroll
        for (int i = 0; i < 4; i++) {
            const int r = rb + 16 * i;
            uint2 o;
            o.x = h2u(__floats2half2_rn(tile[4*c4    ][r], tile[4*c4 + 1][r]));
            o.y = h2u(__floats2half2_rn(tile[4*c4 + 2][r], tile[4*c4 + 3][r]));
            *(uint2*)(g_WTh + (size_t)(n0 + r) * HID + k0 + 4*c4) = o;
        }
    }
}

// ---------------- GEMM mainloop (R12 config, unchanged) ----------------------
__device__ __forceinline__ void gemm_mainloop_f16(
    const __half* __restrict__ Ag, const __half* __restrict__ Bg,
    int m0, int n0, int K,
    float (&acc)[2][8][4], char* sm)
{
    const int tid  = threadIdx.x;
    const int lane = tid & 31;
    const int wid  = tid >> 5;              // 0..7
    const int warp_m = wid & 3, warp_n = wid >> 2;   // 4m x 2n
    const uint32_t sbase = smem_u32(sm);

    const int a_row = warp_m * 32 + (lane & 15);
    const int a_col = (lane >> 4) << 3;
    const int b_row = warp_n * 64 + ((lane >> 4) << 3) + (lane & 7);
    const int b_col = ((lane >> 3) & 1) << 3;

    int rr_[4], ff_[4];
    #pragma unroll
    for (int i = 0; i < 4; i++) {
        int idx = i * 256 + tid;
        rr_[i] = idx >> 3;
        ff_[i] = (idx & 7) * 8;
    }

    const int NK = K / BK;

    #define ISSUE_FULL(s, kc) do { \
        const uint32_t a_s = sbase + (s) * STAGE_BYTES; \
        const int kof = (kc) * BK; \
        _Pragma("unroll") \
        for (int i = 0; i < 4; i++) { \
            cp16(a_s + (rr_[i] * PAD_H + ff_[i]) * 2,           Ag + (size_t)(m0 + rr_[i]) * K + kof + ff_[i]); \
            cp16(a_s + A_BYTES + (rr_[i] * PAD_H + ff_[i]) * 2, Bg + (size_t)(n0 + rr_[i]) * K + kof + ff_[i]); \
        } \
        CP_COMMIT(); \
    } while (0)

    ISSUE_FULL(0, 0);
    ISSUE_FULL(1, 1);

    uint32_t afb[2][2][4];
    uint32_t bfb[2][4];

    for (int kc = 0; kc < NK; kc++) {
        CP_WAIT1();
        __syncthreads();

        const uint32_t as_b = sbase + (kc % 3) * STAGE_BYTES;
        const uint32_t bs_b = as_b + A_BYTES;
        const uint32_t wr_s = sbase + ((kc + 2) % 3) * STAGE_BYTES;
        const bool do_issue = (kc + 2 < NK);
        const int kof = (kc + 2) * BK;

        ldsm_x4(afb[0][0], as_b + ((a_row       * PAD_H) + a_col) * 2);
        ldsm_x4(afb[0][1], as_b + (((a_row + 16) * PAD_H) + a_col) * 2);
        ldsm_x4(bfb[0],    bs_b + ((b_row       * PAD_H) + b_col) * 2);

        #pragma unroll
        for (int ks16 = 0; ks16 < 4; ks16++) {
            const int ks = ks16 * 16;
            if (do_issue) {
                cp16(wr_s + (rr_[ks16] * PAD_H + ff_[ks16]) * 2,
                     Ag + (size_t)(m0 + rr_[ks16]) * K + kof + ff_[ks16]);
                cp16(wr_s + A_BYTES + (rr_[ks16] * PAD_H + ff_[ks16]) * 2,
                     Bg + (size_t)(n0 + rr_[ks16]) * K + kof + ff_[ks16]);
            }
            #pragma unroll
            for (int p = 0; p < 4; p++) {
                if (p < 3)
                    ldsm_x4(bfb[(p + 1) & 1],
                            bs_b + (((b_row + (p + 1) * 16) * PAD_H) + ks + b_col) * 2);
                else if (ks16 < 3)
                    ldsm_x4(bfb[0],
                            bs_b + ((b_row * PAD_H) + ks + 16 + b_col) * 2);
                if (p == 0 && ks16 < 3) {
                    ldsm_x4(afb[(ks16 + 1) & 1][0],
                            as_b + ((a_row * PAD_H) + ks + 16 + a_col) * 2);
                    ldsm_x4(afb[(ks16 + 1) & 1][1],
                            as_b + (((a_row + 16) * PAD_H) + ks + 16 + a_col) * 2);
                }
                const uint32_t* bfc = bfb[p & 1];
                mma_f16(acc[0][2*p],     afb[ks16 & 1][0], &bfc[0]);
                mma_f16(acc[0][2*p + 1], afb[ks16 & 1][0], &bfc[2]);
                mma_f16(acc[1][2*p],     afb[ks16 & 1][1], &bfc[0]);
                mma_f16(acc[1][2*p + 1], afb[ks16 & 1][1], &bfc[2]);
            }
        }
        CP_COMMIT();
    }
    #undef ISSUE_FULL
}

// ---------------- QKV projection (+bias, +RoPE) + Wo transpose tail ----------
#define QKV_BX (NTOT/128)              /* 40 */
#define QKV_B  (QKV_BX*(TSEQ/128))     /* 480 */
#define WO_BX  (NOUT/64)               /* 45 */
#define WO_B   (WO_BX*(QC/64))         /* 2880 */

__global__ __launch_bounds__(GEMM_THREADS) void qkv_mma(
    const int* __restrict__ positions,
    const float* __restrict__ bq, const float* __restrict__ bk,
    const float* __restrict__ bv, const float* __restrict__ Wo)
{
    extern __shared__ char sm[];
    const int tid  = threadIdx.x;

    if (blockIdx.x >= QKV_B) {
        float (*tile)[65] = (float(*)[65])sm;
        const int bb = blockIdx.x - QKV_B;
        const int n0 = (bb % WO_BX) * 64, k0 = (bb / WO_BX) * 64;
        {
            const int tx = tid & 63, ty = tid >> 6;
            #pragma unroll
            for (int i = 0; i < 64; i += 4)
                tile[ty + i][tx] = Wo[(size_t)(k0 + ty + i) * NOUT + n0 + tx];
        }
        __syncthreads();
        {
            const int c4 = tid & 15, rb = tid >> 4;
            #pragma unroll
            for (int i = 0; i < 4; i++) {
                const int r = rb + 16 * i;
                uint2 o;
                o.x = h2u(__floats2half2_rn(tile[4*c4    ][r], tile[4*c4 + 1][r]));
                o.y = h2u(__floats2half2_rn(tile[4*c4 + 2][r], tile[4*c4 + 3][r]));
                *(uint2*)(g_WoTh + (size_t)(n0 + r) * QC + k0 + 4*c4) = o;
            }
        }
        return;
    }

    const int lane = tid & 31;
    const int wid  = tid >> 5;
    const int warp_m = wid & 3, warp_n = wid >> 2;
    const int gid = lane >> 2, tig = lane & 3;
    const int m0 = (blockIdx.x / QKV_BX) * 128, n0 = (blockIdx.x % QKV_BX) * 128;

    const float* bias; __half* outp; int ldout, nloc0, do_rope;
    if (n0 < QC)            { bias = bq; outp = g_Qh; ldout = QC;  nloc0 = n0;            do_rope = 1; }
    else if (n0 < QC + KVC) { bias = bk; outp = g_Kh; ldout = KVC; nloc0 = n0 - QC;       do_rope = 1; }
    else                    { bias = bv; outp = g_Vh; ldout = KVC; nloc0 = n0 - QC - KVC; do_rope = 0; }

    float acc[2][8][4];
    #pragma unroll
    for (int a = 0; a < 2; a++)
        #pragma unroll
        for (int b = 0; b < 8; b++)
            #pragma unroll
            for (int d = 0; d < 4; d++) acc[a][b][d] = 0.f;

    gemm_mainloop_f16(g_Xh, g_WTh, m0, n0, HID, acc, sm);

    #pragma unroll
    for (int mt = 0; mt < 2; mt++) {
        const int t_lo = m0 + warp_m * 32 + mt * 16 + gid;
        const int t_hi = t_lo + 8;
        float pos_lo = 0.f, pos_hi = 0.f;
        if (do_rope) { pos_lo = (float)positions[t_lo]; pos_hi = (float)positions[t_hi]; }
        #pragma unroll
        for (int nt = 0; nt < 8; nt++) {
            const int c = nloc0 + warp_n * 64 + nt * 8 + 2 * tig;
            const float b0 = bias[c], b1 = bias[c + 1];
            float v0 = acc[mt][nt][0] + b0, v1 = acc[mt][nt][1] + b1;
            float v2 = acc[mt][nt][2] + b0, v3 = acc[mt][nt][3] + b1;
            if (do_rope) {
                const int ip = (c & (DH - 1)) >> 1;
                const float inv_eff = 0.515625f * exp2f(-(float)ip * L2THETA_OVER_32);
                float s, co;
                __sincosf(pos_lo * (1.0f / 32.0f) * inv_eff, &s, &co);
                float e = v0 * co - v1 * s; v1 = v0 * s + v1 * co; v0 = e;
                __sincosf(pos_hi * (1.0f / 32.0f) * inv_eff, &s, &co);
                e = v2 * co - v3 * s; v3 = v2 * s + v3 * co; v2 = e;
            }
            *(__half2*)(outp + (size_t)t_lo * ldout + c) = __floats2half2_rn(v0, v1);
            *(__half2*)(outp + (size_t)t_hi * ldout + c) = __floats2half2_rn(v2, v3);
        }
    }
}

// ---------------- output projection (+bias) ----------------------------------
__global__ __launch_bounds__(GEMM_THREADS) void out_mma(
    const float* __restrict__ bo, float* __restrict__ out)
{
    extern __shared__ char sm[];
    const int tid  = threadIdx.x;
    const int lane = tid & 31;
    const int wid  = tid >> 5;
    const int warp_m = wid & 3, warp_n = wid >> 2;
    const int gid = lane >> 2, tig = lane & 3;
    const int m0 = blockIdx.y * 128, n0 = blockIdx.x * 128;

    float acc[2][8][4];
    #pragma unroll
    for (int a = 0; a < 2; a++)
        #pragma unroll
        for (int b = 0; b < 8; b++)
            #pragma unroll
            for (int d = 0; d < 4; d++) acc[a][b][d] = 0.f;

    gemm_mainloop_f16(g_Yh, g_WoTh, m0, n0, QC, acc, sm);

    #pragma unroll
    for (int mt = 0; mt < 2; mt++) {
        const int t_lo = m0 + warp_m * 32 + mt * 16 + gid;
        const int t_hi = t_lo + 8;
        #pragma unroll
        for (int nt = 0; nt < 8; nt++) {
            const int c = n0 + warp_n * 64 + nt * 8 + 2 * tig;
            if (c < NOUT) {
                const float b0 = bo[c], b1 = bo[c + 1];
                *(float2*)(out + (size_t)t_lo * NOUT + c) =
                    make_float2(acc[mt][nt][0] + b0, acc[mt][nt][1] + b1);
                *(float2*)(out + (size_t)t_hi * NOUT + c) =
                    make_float2(acc[mt][nt][2] + b0, acc[mt][nt][3] + b1);
            }
        }
    }
}

// ---------------- flash attention: 2 heads/block, P in registers, V via trans
#define KS_H2 72                        /* 144B rows -> LDSM conflict-free */
#define AOFF_VS (64*KS_H2*2)
#define ATT_SMEM (2*64*KS_H2*2)         /* 18432 */
#define NQB    (TSEQ/64)                /* 24 */
#define ATT_B  (NQB*(NHEAD/2))          /* 768 */

__global__ __launch_bounds__(256) void attn_mma(
    const int* __restrict__ is_slide_p, const int* __restrict__ win_p)
{
    extern __shared__ char sm[];
    const int tid = threadIdx.x;

    __half (*Ks)[KS_H2] = (__half(*)[KS_H2])(sm);
    __half (*Vs)[KS_H2] = (__half(*)[KS_H2])(sm + AOFF_VS);
    const uint32_t ks_b = smem_u32(sm);
    const uint32_t vs_b = ks_b + AOFF_VS;

    const int lane = tid & 31, wid = tid >> 5;   // 8 warps
    const int wid4 = wid & 3, hsel = wid >> 2;   // 4 warps per head
    const int gid = lane >> 2, tig = lane & 3;
    const int t0   = (blockIdx.x % NQB) * 64;
    const int pair = blockIdx.x / NQB;           // 0..31
    const int h    = 2 * pair + hsel;
    const int kvh  = pair >> 2;
    const int is_slide = is_slide_p[0], W = win_p[0];

    const int r0 = t0 + wid4 * 16 + gid, r1 = r0 + 8;
    const int rlo0 = is_slide ? r0 - W : 0;
    const int rlo1 = is_slide ? r1 - W : 0;

    // K-fragment (non-trans) lane addressing
    const int ld_nrow  = ((lane >> 4) << 3) + (lane & 7);
    const int ld_bkoff = ((lane >> 3) & 1) << 3;
    // V-fragment (trans) lane addressing: tiles (k0-7,n0-7),(k8-15,n0-7),(k0-7,n8-15),(k8-15,n8-15)
    const int v_row = (((lane >> 3) & 1) << 3) + (lane & 7);
    const int v_col = (lane >> 4) << 3;

    uint32_t qf[4][4];
    {
        const __half* q0 = g_Qh + (size_t)r0 * QC + h * DH;
        const __half* q1 = g_Qh + (size_t)r1 * QC + h * DH;
        #pragma unroll
        for (int kk = 0; kk < 4; kk++) {
            qf[kk][0] = *(const uint32_t*)(q0 + kk * 16 + 2 * tig);
            qf[kk][1] = *(const uint32_t*)(q1 + kk * 16 + 2 * tig);
            qf[kk][2] = *(const uint32_t*)(q0 + kk * 16 + 2 * tig + 8);
            qf[kk][3] = *(const uint32_t*)(q1 + kk * 16 + 2 * tig + 8);
        }
    }

    float oc[8][4];
    #pragma unroll
    for (int nt = 0; nt < 8; nt++)
        #pragma unroll
        for (int d = 0; d < 4; d++) oc[nt][d] = 0.f;
    float m0v = -1e30f, m1v = -1e30f, l0 = 0.f, l1 = 0.f;

    const int cs0 = is_slide ? (max(0, t0 - W) & ~63) : 0;

    for (int cs = cs0; cs <= t0; cs += 64) {
        __syncthreads();
        // stage K and V, both row-major [key][dim]
        #pragma unroll
        for (int i = 0; i < 2; i++) {
            int idx = i * 256 + tid, rr = idx >> 3, c8 = (idx & 7) * 8;
            *(uint4*)&Ks[rr][c8] =
                *(const uint4*)(g_Kh + (size_t)(cs + rr) * KVC + kvh * DH + c8);
            *(uint4*)&Vs[rr][c8] =
                *(const uint4*)(g_Vh + (size_t)(cs + rr) * KVC + kvh * DH + c8);
        }
        __syncthreads();

        // S = Q @ K^T
        float sc[8][4];
        #pragma unroll
        for (int p = 0; p < 4; p++) {
            sc[2*p][0] = sc[2*p][1] = sc[2*p][2] = sc[2*p][3] = 0.f;
            sc[2*p+1][0] = sc[2*p+1][1] = sc[2*p+1][2] = sc[2*p+1][3] = 0.f;
            #pragma unroll
            for (int kk = 0; kk < 4; kk++) {
                uint32_t bf[4];
                ldsm_x4(bf, ks_b + (((p * 16 + ld_nrow) * KS_H2) + kk * 16 + ld_bkoff) * 2);
                mma_f16(sc[2*p],     qf[kk], &bf[0]);
                mma_f16(sc[2*p + 1], qf[kk], &bf[2]);
            }
        }

        // scale + mask + online softmax (P kept in registers as A-fragments)
        float vmax0 = -1e30f, vmax1 = -1e30f;
        #pragma unroll
        for (int nt = 0; nt < 8; nt++) {
            const int s0 = cs + nt * 8 + 2 * tig, s1 = s0 + 1;
            float v0 = (s0 <= r0 && s0 >= rlo0) ? sc[nt][0] * 0.125f : -1e30f;
            float v1 = (s1 <= r0 && s1 >= rlo0) ? sc[nt][1] * 0.125f : -1e30f;
            float v2 = (s0 <= r1 && s0 >= rlo1) ? sc[nt][2] * 0.125f : -1e30f;
            float v3 = (s1 <= r1 && s1 >= rlo1) ? sc[nt][3] * 0.125f : -1e30f;
            sc[nt][0] = v0; sc[nt][1] = v1; sc[nt][2] = v2; sc[nt][3] = v3;
            vmax0 = fmaxf(vmax0, fmaxf(v0, v1));
            vmax1 = fmaxf(vmax1, fmaxf(v2, v3));
        }
        vmax0 = fmaxf(vmax0, __shfl_xor_sync(0xffffffffu, vmax0, 1));
        vmax0 = fmaxf(vmax0, __shfl_xor_sync(0xffffffffu, vmax0, 2));
        vmax1 = fmaxf(vmax1, __shfl_xor_sync(0xffffffffu, vmax1, 1));
        vmax1 = fmaxf(vmax1, __shfl_xor_sync(0xffffffffu, vmax1, 2));

        const float mn0 = fmaxf(m0v, vmax0), mn1 = fmaxf(m1v, vmax1);
        const float a0 = __expf(m0v - mn0), a1 = __expf(m1v - mn1);
        m0v = mn0; m1v = mn1;

        uint32_t ph[8][2];
        float ps0 = 0.f, ps1 = 0.f;
        #pragma unroll
        for (int nt = 0; nt < 8; nt++) {
            float p0 = __expf(sc[nt][0] - mn0), p1 = __expf(sc[nt][1] - mn0);
            float p2 = __expf(sc[nt][2] - mn1), p3 = __expf(sc[nt][3] - mn1);
            ps0 += p0 + p1; ps1 += p2 + p3;
            ph[nt][0] = h2u(__floats2half2_rn(p0, p1));
            ph[nt][1] = h2u(__floats2half2_rn(p2, p3));
        }
        ps0 += __shfl_xor_sync(0xffffffffu, ps0, 1);
        ps0 += __shfl_xor_sync(0xffffffffu, ps0, 2);
        ps1 += __shfl_xor_sync(0xffffffffu, ps1, 1);
        ps1 += __shfl_xor_sync(0xffffffffu, ps1, 2);
        l0 = l0 * a0 + ps0;
        l1 = l1 * a1 + ps1;

        #pragma unroll
        for (int nt = 0; nt < 8; nt++) {
            oc[nt][0] *= a0; oc[nt][1] *= a0;
            oc[nt][2] *= a1; oc[nt][3] *= a1;
        }

        // O += P @ V : A from registers, B via ldmatrix.trans on row-major V
        #pragma unroll
        for (int kk = 0; kk < 4; kk++) {
            uint32_t af[4] = { ph[2*kk][0], ph[2*kk][1], ph[2*kk+1][0], ph[2*kk+1][1] };
            #pragma unroll
            for (int p = 0; p < 4; p++) {
                uint32_t bf[4];
                ldsm_x4_trans(bf, vs_b + (((kk * 16 + v_row) * KS_H2) + p * 16 + v_col) * 2);
                mma_f16(oc[2*p],     af, &bf[0]);
                mma_f16(oc[2*p + 1], af, &bf[2]);
            }
        }
    }

    const float i0 = 1.f / l0, i1 = 1.f / l1;
    #pragma unroll
    for (int nt = 0; nt < 8; nt++) {
        const int c = h * DH + nt * 8 + 2 * tig;
        *(__half2*)(g_Yh + (size_t)r0 * QC + c) =
            __floats2half2_rn(oc[nt][0] * i0, oc[nt][1] * i0);
        *(__half2*)(g_Yh + (size_t)r1 * QC + c) =
            __floats2half2_rn(oc[nt][2] * i1, oc[nt][3] * i1);
    }
}

// ---------------------------------------------------------------------------
extern "C" void kernel_launch(void* const* d_in, const int* in_sizes, int n_in,
                              void* d_out, int out_size)
{
    const float* x         = (const float*)d_in[0];
    const int*   positions = (const int*)  d_in[1];
    const float* Wq        = (const float*)d_in[2];
    const float* bq        = (const float*)d_in[3];
    const float* Wk        = (const float*)d_in[4];
    const float* bk        = (const float*)d_in[5];
    const float* Wv        = (const float*)d_in[6];
    const float* bv        = (const float*)d_in[7];
    const float* Wo        = (const float*)d_in[8];
    const float* bo        = (const float*)d_in[9];
    const int*   is_slide  = (const int*)  d_in[10];
    const int*   win       = (const int*)  d_in[11];

    cudaFuncSetAttribute(attn_mma, cudaFuncAttributeMaxDynamicSharedMemorySize, ATT_SMEM);
    cudaFuncSetAttribute(qkv_mma,  cudaFuncAttributeMaxDynamicSharedMemorySize, GEMM_SMEM);
    cudaFuncSetAttribute(out_mma,  cudaFuncAttributeMaxDynamicSharedMemorySize, GEMM_SMEM);

    prep_qkv<<<PREP_B, 256>>>(x, Wq, Wk, Wv);

    qkv_mma<<<QKV_B + WO_B, GEMM_THREADS, GEMM_SMEM>>>(positions, bq, bk, bv, Wo);

    attn_mma<<<ATT_B, 256, ATT_SMEM>>>(is_slide, win);

    out_mma<<<dim3(NOUT_PAD / 128, TSEQ / 128), GEMM_THREADS, GEMM_SMEM>>>(bo, (float*)d_out);
}